// round 1
// baseline (speedup 1.0000x reference)
#include <cuda_runtime.h>
#include <cuda_bf16.h>
#include <cstdint>

// Problem constants (shapes are fixed by the dataset)
#define NMAX 100000
#define EMAX 1600000
#define FDIM 128

// ---------------- device scratch (no runtime allocation allowed) ------------
__device__ int   g_ptr[NMAX + 1];
__device__ int   g_cursor[NMAX];
__device__ int   g_col[EMAX];
__device__ float g_agg[(size_t)NMAX * FDIM];
__device__ float g_hA [(size_t)NMAX * FDIM];
__device__ float g_hB [(size_t)NMAX * FDIM];
__device__ int   g_is32;

// buffer selectors: 0=g_agg 1=g_hA 2=g_hB 3=external
__device__ __forceinline__ const float* pick_c(int s, const float* ext) {
    return s == 0 ? g_agg : s == 1 ? g_hA : s == 2 ? g_hB : ext;
}
__device__ __forceinline__ float* pick_m(int s, float* ext) {
    return s == 0 ? g_agg : s == 1 ? g_hA : s == 2 ? g_hB : ext;
}

// ---------------- CSR build --------------------------------------------------
__global__ void k_zero_ptr(int n) {            // zero g_ptr[0..n]
    int i = blockIdx.x * blockDim.x + threadIdx.x;
    if (i <= n) g_ptr[i] = 0;
}

// Detect whether edge_index is really int64 or int32 reinterpreted.
__global__ void k_detect(const long long* __restrict__ e, int E, int nNodes) {
    if (blockIdx.x == 0 && threadIdx.x == 0) {
        int bad = 0;
        int lim = E < 64 ? E : 64;
        for (int i = 0; i < lim; i++) {
            long long v = e[i];
            if (v < 0 || v >= (long long)nNodes) bad = 1;
        }
        g_is32 = bad;
    }
}

__global__ void k_hist(const long long* __restrict__ e64, int E) {
    int i = blockIdx.x * blockDim.x + threadIdx.x;
    if (i >= E) return;
    int d;
    if (!g_is32) d = (int)e64[(size_t)E + i];
    else         d = ((const int*)e64)[(size_t)E + i];
    atomicAdd(&g_ptr[d + 1], 1);
}

// single-block inclusive scan of g_ptr[0..n-1]
__global__ void k_scan(int n) {
    __shared__ int wsum[32];
    __shared__ int carry;
    int t = threadIdx.x;
    int lane = t & 31, wid = t >> 5;
    if (t == 0) carry = 0;
    __syncthreads();
    for (int base = 0; base < n; base += 1024) {
        int i = base + t;
        int v = (i < n) ? g_ptr[i] : 0;
        #pragma unroll
        for (int o = 1; o < 32; o <<= 1) {
            int u = __shfl_up_sync(0xFFFFFFFFu, v, o);
            if (lane >= o) v += u;
        }
        if (lane == 31) wsum[wid] = v;
        __syncthreads();
        if (wid == 0) {
            int w = wsum[lane];
            #pragma unroll
            for (int o = 1; o < 32; o <<= 1) {
                int u = __shfl_up_sync(0xFFFFFFFFu, w, o);
                if (lane >= o) w += u;
            }
            wsum[lane] = w;
        }
        __syncthreads();
        int add = carry + (wid > 0 ? wsum[wid - 1] : 0);
        if (i < n) g_ptr[i] = v + add;
        int total = wsum[31];
        __syncthreads();
        if (t == 0) carry += total;
        __syncthreads();
    }
}

__global__ void k_copy_cursor(int n) {
    int i = blockIdx.x * blockDim.x + threadIdx.x;
    if (i < n) g_cursor[i] = g_ptr[i];
}

__global__ void k_fill(const long long* __restrict__ e64, int E) {
    int i = blockIdx.x * blockDim.x + threadIdx.x;
    if (i >= E) return;
    int s, d;
    if (!g_is32) {
        s = (int)e64[i];
        d = (int)e64[(size_t)E + i];
    } else {
        const int* e32 = (const int*)e64;
        s = e32[i];
        d = e32[(size_t)E + i];
    }
    int pos = atomicAdd(&g_cursor[d], 1);
    g_col[pos] = s;
}

// ---------------- mean aggregation (gather, warp per node) ------------------
__global__ void k_aggregate(const float* __restrict__ ext, int selIn, int nNodes) {
    const float* __restrict__ X = pick_c(selIn, ext);
    int node = (blockIdx.x * blockDim.x + threadIdx.x) >> 5;
    int lane = threadIdx.x & 31;
    if (node >= nNodes) return;
    int start = g_ptr[node], end = g_ptr[node + 1];
    float4 acc = make_float4(0.f, 0.f, 0.f, 0.f);
    for (int i = start; i < end; i++) {
        int s = g_col[i];
        float4 v = *(const float4*)(X + (size_t)s * FDIM + lane * 4);
        acc.x += v.x; acc.y += v.y; acc.z += v.z; acc.w += v.w;
    }
    float dinv = 1.f / fmaxf((float)(end - start), 1.f);
    acc.x *= dinv; acc.y *= dinv; acc.z *= dinv; acc.w *= dinv;
    *(float4*)(g_agg + (size_t)node * FDIM + lane * 4) = acc;
}

// ---------------- fused dual GEMM: Y = agg@Wl^T + Ax@Wr^T + b ---------------
// Block: 128 nodes x DOUT outs, 256 threads, each thread 8 nodes x (DOUT/16) outs.
template <int DOUT>
__global__ __launch_bounds__(256, 2)
void k_gemm(const float* __restrict__ extAx, int selAx,
            const float* __restrict__ Wl, const float* __restrict__ Wr,
            const float* __restrict__ bias,
            float* __restrict__ extY, int selY, int nNodes) {
    constexpr int TO   = DOUT / 16;            // outs per thread (8 or 4)
    constexpr int PAD  = FDIM + 4;             // 132 floats, 16B-aligned stride
    constexpr int PADW = (DOUT == 128) ? 132 : 68;
    __shared__ float sA[32 * PAD];
    __shared__ float sW[32 * PADW];

    const float* __restrict__ Ax = pick_c(selAx, extAx);
    float* __restrict__ Y = pick_m(selY, extY);

    const int tx = threadIdx.x;
    const int ng = tx >> 4;                    // 0..15 node group (8 nodes)
    const int og = tx & 15;                    // 0..15 out group (TO outs)
    const int nodeBase = blockIdx.x * 128;

    float acc[8][TO];
    #pragma unroll
    for (int i = 0; i < 8; i++)
        #pragma unroll
        for (int j = 0; j < TO; j++) acc[i][j] = 0.f;

    #pragma unroll
    for (int phase = 0; phase < 2; phase++) {
        const float* __restrict__ A = phase ? Ax : g_agg;
        const float* __restrict__ W = phase ? Wr : Wl;
        for (int kb = 0; kb < FDIM; kb += 32) {
            __syncthreads();
            // A tile: [128 nodes][32 k] -> sA[k][node]
            #pragma unroll
            for (int r = 0; r < 4; r++) {
                int lin = tx + r * 256;          // 0..1023 float4 slots
                int node = lin >> 3;
                int kv = lin & 7;
                int gn = nodeBase + node;
                float4 v = make_float4(0.f, 0.f, 0.f, 0.f);
                if (gn < nNodes)
                    v = *(const float4*)(A + (size_t)gn * FDIM + kb + kv * 4);
                sA[(kv * 4 + 0) * PAD + node] = v.x;
                sA[(kv * 4 + 1) * PAD + node] = v.y;
                sA[(kv * 4 + 2) * PAD + node] = v.z;
                sA[(kv * 4 + 3) * PAD + node] = v.w;
            }
            // W tile: [DOUT][32 k] -> sW[k][out]
            #pragma unroll
            for (int r = 0; r < DOUT / 32; r++) {
                int lin = tx + r * 256;
                int out = lin >> 3;
                int kv = lin & 7;
                float4 v = *(const float4*)(W + out * FDIM + kb + kv * 4);
                sW[(kv * 4 + 0) * PADW + out] = v.x;
                sW[(kv * 4 + 1) * PADW + out] = v.y;
                sW[(kv * 4 + 2) * PADW + out] = v.z;
                sW[(kv * 4 + 3) * PADW + out] = v.w;
            }
            __syncthreads();
            #pragma unroll 8
            for (int k = 0; k < 32; k++) {
                float4 a0 = *(const float4*)&sA[k * PAD + ng * 8];
                float4 a1 = *(const float4*)&sA[k * PAD + ng * 8 + 4];
                float a[8] = {a0.x, a0.y, a0.z, a0.w, a1.x, a1.y, a1.z, a1.w};
                float w[TO];
                if (TO == 8) {
                    float4 w0 = *(const float4*)&sW[k * PADW + og * TO];
                    float4 w1 = *(const float4*)&sW[k * PADW + og * TO + 4];
                    w[0] = w0.x; w[1] = w0.y; w[2] = w0.z; w[3] = w0.w;
                    w[4] = w1.x; w[5] = w1.y; w[6] = w1.z; w[7] = w1.w;
                } else {
                    float4 w0 = *(const float4*)&sW[k * PADW + og * TO];
                    w[0] = w0.x; w[1] = w0.y; w[2] = w0.z; w[3] = w0.w;
                }
                #pragma unroll
                for (int i = 0; i < 8; i++)
                    #pragma unroll
                    for (int j = 0; j < TO; j++)
                        acc[i][j] += a[i] * w[j];
            }
        }
    }
    // epilogue: + bias, write
    #pragma unroll
    for (int i = 0; i < 8; i++) {
        int gn = nodeBase + ng * 8 + i;
        if (gn < nNodes) {
            #pragma unroll
            for (int j = 0; j < TO; j++) {
                int o = og * TO + j;
                Y[(size_t)gn * DOUT + o] = acc[i][j] + bias[o];
            }
        }
    }
}

// ---------------- fused ReLU + LayerNorm (warp per node, F=128) -------------
__global__ void k_relu_ln(const float* __restrict__ gamma,
                          const float* __restrict__ beta,
                          int selOut, int nNodes) {
    int node = (blockIdx.x * blockDim.x + threadIdx.x) >> 5;
    int lane = threadIdx.x & 31;
    if (node >= nNodes) return;
    float* __restrict__ H = pick_m(selOut, nullptr);
    float4 v = *(const float4*)(g_agg + (size_t)node * FDIM + lane * 4);
    v.x = fmaxf(v.x, 0.f); v.y = fmaxf(v.y, 0.f);
    v.z = fmaxf(v.z, 0.f); v.w = fmaxf(v.w, 0.f);
    float s = v.x + v.y + v.z + v.w;
    #pragma unroll
    for (int o = 16; o; o >>= 1) s += __shfl_xor_sync(0xFFFFFFFFu, s, o);
    float mu = s * (1.f / 128.f);
    float dx = v.x - mu, dy = v.y - mu, dz = v.z - mu, dw = v.w - mu;
    float q = dx * dx + dy * dy + dz * dz + dw * dw;
    #pragma unroll
    for (int o = 16; o; o >>= 1) q += __shfl_xor_sync(0xFFFFFFFFu, q, o);
    float rstd = rsqrtf(q * (1.f / 128.f) + 1e-5f);
    float4 g4 = *(const float4*)(gamma + lane * 4);
    float4 b4 = *(const float4*)(beta + lane * 4);
    float4 o4;
    o4.x = dx * rstd * g4.x + b4.x;
    o4.y = dy * rstd * g4.y + b4.y;
    o4.z = dz * rstd * g4.z + b4.z;
    o4.w = dw * rstd * g4.w + b4.w;
    *(float4*)(H + (size_t)node * FDIM + lane * 4) = o4;
}

// ---------------- launch -----------------------------------------------------
extern "C" void kernel_launch(void* const* d_in, const int* in_sizes, int n_in,
                              void* d_out, int out_size) {
    const float* x = (const float*)d_in[0];
    const long long* edges = (const long long*)d_in[1];
    const int E = in_sizes[1] / 2;
    const int N = in_sizes[0] / FDIM;

    const float *Wl0, *Wr0, *b0, *g0, *be0;
    const float *Wl1, *Wr1, *b1, *g1, *be1;
    const float *Wl2, *Wr2, *b2;
    if (in_sizes[5] == 16384) {
        // dict insertion order: Wl0,Wr0,b0, Wl1,Wr1,b1, Wl2,Wr2,b2, g0,be0,g1,be1
        Wl0 = (const float*)d_in[2];  Wr0 = (const float*)d_in[3];  b0 = (const float*)d_in[4];
        Wl1 = (const float*)d_in[5];  Wr1 = (const float*)d_in[6];  b1 = (const float*)d_in[7];
        Wl2 = (const float*)d_in[8];  Wr2 = (const float*)d_in[9];  b2 = (const float*)d_in[10];
        g0  = (const float*)d_in[11]; be0 = (const float*)d_in[12];
        g1  = (const float*)d_in[13]; be1 = (const float*)d_in[14];
    } else {
        // signature order: Wl0,Wr0,b0,g0,be0, Wl1,Wr1,b1,g1,be1, Wl2,Wr2,b2
        Wl0 = (const float*)d_in[2];  Wr0 = (const float*)d_in[3];  b0 = (const float*)d_in[4];
        g0  = (const float*)d_in[5];  be0 = (const float*)d_in[6];
        Wl1 = (const float*)d_in[7];  Wr1 = (const float*)d_in[8];  b1 = (const float*)d_in[9];
        g1  = (const float*)d_in[10]; be1 = (const float*)d_in[11];
        Wl2 = (const float*)d_in[12]; Wr2 = (const float*)d_in[13]; b2 = (const float*)d_in[14];
    }
    float* out = (float*)d_out;

    const int TB = 256;
    const int gE = (E + TB - 1) / TB;
    const int gN = (N + TB - 1) / TB;
    const int gWarp = (N * 32 + TB - 1) / TB;     // warp-per-node kernels
    const int gGemm = (N + 127) / 128;

    // CSR build (once per call; reused by all 3 layers)
    k_zero_ptr<<<(N + 1 + TB) / TB, TB>>>(N);
    k_detect<<<1, 1>>>(edges, E, N);
    k_hist<<<gE, TB>>>(edges, E);
    k_scan<<<1, 1024>>>(N + 1);
    k_copy_cursor<<<gN, TB>>>(N);
    k_fill<<<gE, TB>>>(edges, E);

    // Layer 0: agg(x) -> gemm -> relu+LN -> hA
    k_aggregate<<<gWarp, TB>>>(x, 3, N);
    k_gemm<128><<<gGemm, TB>>>(x, 3, Wl0, Wr0, b0, nullptr, 0, N);
    k_relu_ln<<<gWarp, TB>>>(g0, be0, 1, N);

    // Layer 1: agg(hA) -> gemm -> relu+LN -> hB
    k_aggregate<<<gWarp, TB>>>(nullptr, 1, N);
    k_gemm<128><<<gGemm, TB>>>(nullptr, 1, Wl1, Wr1, b1, nullptr, 0, N);
    k_relu_ln<<<gWarp, TB>>>(g1, be1, 2, N);

    // Layer 2: agg(hB) -> gemm(DOUT=64) -> d_out
    k_aggregate<<<gWarp, TB>>>(nullptr, 2, N);
    k_gemm<64><<<gGemm, TB>>>(nullptr, 2, Wl2, Wr2, b2, out, 3, N);
}

// round 3
// speedup vs baseline: 1.2073x; 1.2073x over previous
#include <cuda_runtime.h>
#include <cuda_bf16.h>
#include <cstdint>

#define NMAX 100000
#define EMAX 1600000
#define FDIM 128

// ---------------- device scratch --------------------------------------------
__device__ int   g_ptr[NMAX + 1];
__device__ int   g_cursor[NMAX];
__device__ int   g_cnt[NMAX];
__device__ int   g_scan[NMAX];
__device__ int   g_bsum[512];
__device__ int   g_boff[512];
__device__ int   g_col[EMAX];
__device__ float g_agg[(size_t)NMAX * FDIM];
__device__ float g_hA [(size_t)NMAX * FDIM];
__device__ float g_hB [(size_t)NMAX * FDIM];
__device__ int   g_is32;

__device__ __forceinline__ const float* pick_c(int s, const float* ext) {
    return s == 0 ? g_agg : s == 1 ? g_hA : s == 2 ? g_hB : ext;
}
__device__ __forceinline__ float* pick_m(int s, float* ext) {
    return s == 0 ? g_agg : s == 1 ? g_hA : s == 2 ? g_hB : ext;
}

// ---------------- packed f32x2 helpers ---------------------------------------
__device__ __forceinline__ void fma2(unsigned long long& d,
                                     unsigned long long a,
                                     unsigned long long b) {
    asm("fma.rn.f32x2 %0, %1, %2, %0;" : "+l"(d) : "l"(a), "l"(b));
}
__device__ __forceinline__ unsigned long long rep2(float x) {
    unsigned long long r;
    asm("mov.b64 %0, {%1, %1};" : "=l"(r) : "f"(x));
    return r;
}
__device__ __forceinline__ float2 unpack2(unsigned long long v) {
    float2 r;
    asm("mov.b64 {%0, %1}, %2;" : "=f"(r.x), "=f"(r.y) : "l"(v));
    return r;
}

// ---------------- CSR build --------------------------------------------------
__global__ void k_zero_detect(const long long* __restrict__ e, int E, int n) {
    int i = blockIdx.x * blockDim.x + threadIdx.x;
    if (i < n) g_cnt[i] = 0;
    if (i == 0) {
        int bad = 0;
        int lim = E < 64 ? E : 64;
        for (int j = 0; j < lim; j++) {
            long long v = e[j];
            if (v < 0 || v >= (long long)n) bad = 1;
        }
        g_is32 = bad;
    }
}

__global__ void k_hist(const long long* __restrict__ e64, int E) {
    int i = blockIdx.x * blockDim.x + threadIdx.x;
    if (i >= E) return;
    int d;
    if (!g_is32) d = (int)e64[(size_t)E + i];
    else         d = ((const int*)e64)[(size_t)E + i];
    atomicAdd(&g_cnt[d], 1);
}

// block-level inclusive scan of g_cnt -> g_scan, block totals -> g_bsum
__global__ void k_blockscan(int n) {
    __shared__ int wsum[8];
    int i = blockIdx.x * 256 + threadIdx.x;
    int lane = threadIdx.x & 31, wid = threadIdx.x >> 5;
    int v = (i < n) ? g_cnt[i] : 0;
    #pragma unroll
    for (int o = 1; o < 32; o <<= 1) {
        int u = __shfl_up_sync(0xFFFFFFFFu, v, o);
        if (lane >= o) v += u;
    }
    if (lane == 31) wsum[wid] = v;
    __syncthreads();
    if (wid == 0 && lane < 8) {
        int w = wsum[lane];
        #pragma unroll
        for (int o = 1; o < 8; o <<= 1) {
            int u = __shfl_up_sync(0xFFu, w, o);
            if (lane >= o) w += u;
        }
        wsum[lane] = w;
    }
    __syncthreads();
    int incl = v + (wid > 0 ? wsum[wid - 1] : 0);
    if (i < n) g_scan[i] = incl;
    if (threadIdx.x == 255) g_bsum[blockIdx.x] = incl;
}

// single-block scan over block sums -> exclusive offsets g_boff
__global__ void k_scan_bsum(int nb) {
    __shared__ int wsum[16];
    int t = threadIdx.x;
    int lane = t & 31, wid = t >> 5;
    if (nb > 512) nb = 512;
    int v = (t < nb) ? g_bsum[t] : 0;
    int orig = v;
    #pragma unroll
    for (int o = 1; o < 32; o <<= 1) {
        int u = __shfl_up_sync(0xFFFFFFFFu, v, o);
        if (lane >= o) v += u;
    }
    if (lane == 31) wsum[wid] = v;
    __syncthreads();
    if (wid == 0 && lane < 16) {
        int w = wsum[lane];
        #pragma unroll
        for (int o = 1; o < 16; o <<= 1) {
            int u = __shfl_up_sync(0xFFFFu, w, o);
            if (lane >= o) w += u;
        }
        wsum[lane] = w;
    }
    __syncthreads();
    int incl = v + (wid > 0 ? wsum[wid - 1] : 0);
    if (t < nb) g_boff[t] = incl - orig;
}

__global__ void k_finalize(int n) {
    int i = blockIdx.x * 256 + threadIdx.x;
    if (i >= n) return;
    int incl = g_scan[i] + g_boff[blockIdx.x];
    g_ptr[i + 1] = incl;
    g_cursor[i] = incl - g_cnt[i];
    if (i == 0) g_ptr[0] = 0;
}

__global__ void k_fill(const long long* __restrict__ e64, int E) {
    int i = blockIdx.x * blockDim.x + threadIdx.x;
    if (i >= E) return;
    int s, d;
    if (!g_is32) {
        s = (int)e64[i];
        d = (int)e64[(size_t)E + i];
    } else {
        const int* e32 = (const int*)e64;
        s = e32[i];
        d = e32[(size_t)E + i];
    }
    int pos = atomicAdd(&g_cursor[d], 1);
    g_col[pos] = s;
}

// ---------------- mean aggregation (gather, warp per node) ------------------
__global__ void k_aggregate(const float* __restrict__ ext, int selIn, int nNodes) {
    const float* __restrict__ X = pick_c(selIn, ext);
    int node = (blockIdx.x * blockDim.x + threadIdx.x) >> 5;
    int lane = threadIdx.x & 31;
    if (node >= nNodes) return;
    int start = g_ptr[node], end = g_ptr[node + 1];
    float4 acc = make_float4(0.f, 0.f, 0.f, 0.f);
    for (int i = start; i < end; i++) {
        int s = g_col[i];
        float4 v = *(const float4*)(X + (size_t)s * FDIM + lane * 4);
        acc.x += v.x; acc.y += v.y; acc.z += v.z; acc.w += v.w;
    }
    float dinv = 1.f / fmaxf((float)(end - start), 1.f);
    acc.x *= dinv; acc.y *= dinv; acc.z *= dinv; acc.w *= dinv;
    *(float4*)(g_agg + (size_t)node * FDIM + lane * 4) = acc;
}

// ---------------- fused dual GEMM + bias (+ReLU+LN) --------------------------
// Y = f(agg@Wl^T + Ax@Wr^T + b); block = 128 nodes x DOUT, 256 threads,
// thread = 8 nodes x TO outs, acc packed f32x2 along node pairs.
template <int DOUT, bool LN>
__global__ __launch_bounds__(256, 2)
void k_gemm(const float* __restrict__ extAx, int selAx,
            const float* __restrict__ Wl, const float* __restrict__ Wr,
            const float* __restrict__ bias,
            const float* __restrict__ gamma, const float* __restrict__ beta,
            float* __restrict__ extY, int selY, int nNodes) {
    constexpr int TO   = DOUT / 16;            // 8 or 4 outs per thread
    constexpr int PAD  = FDIM + 4;             // 132
    constexpr int PADW = (DOUT == 128) ? 132 : 68;
    __shared__ float sA[32 * PAD];
    __shared__ float sW[32 * PADW];

    const float* __restrict__ Ax = pick_c(selAx, extAx);
    float* __restrict__ Y = pick_m(selY, extY);

    const int tx = threadIdx.x;
    const int ng = tx >> 4;                    // node group (8 nodes)
    const int og = tx & 15;                    // out group (TO outs)
    const int nodeBase = blockIdx.x * 128;

    unsigned long long acc2[4][TO];            // [node pair][out], f32x2
    #pragma unroll
    for (int i = 0; i < 4; i++)
        #pragma unroll
        for (int j = 0; j < TO; j++) acc2[i][j] = 0ULL;

    #pragma unroll
    for (int phase = 0; phase < 2; phase++) {
        const float* __restrict__ A = phase ? Ax : g_agg;
        const float* __restrict__ W = phase ? Wr : Wl;
        for (int kb = 0; kb < FDIM; kb += 32) {
            __syncthreads();
            #pragma unroll
            for (int r = 0; r < 4; r++) {
                int lin = tx + r * 256;
                int node = lin >> 3;
                int kv = lin & 7;
                int gn = nodeBase + node;
                float4 v = make_float4(0.f, 0.f, 0.f, 0.f);
                if (gn < nNodes)
                    v = *(const float4*)(A + (size_t)gn * FDIM + kb + kv * 4);
                sA[(kv * 4 + 0) * PAD + node] = v.x;
                sA[(kv * 4 + 1) * PAD + node] = v.y;
                sA[(kv * 4 + 2) * PAD + node] = v.z;
                sA[(kv * 4 + 3) * PAD + node] = v.w;
            }
            #pragma unroll
            for (int r = 0; r < DOUT / 32; r++) {
                int lin = tx + r * 256;
                int out = lin >> 3;
                int kv = lin & 7;
                float4 v = *(const float4*)(W + out * FDIM + kb + kv * 4);
                sW[(kv * 4 + 0) * PADW + out] = v.x;
                sW[(kv * 4 + 1) * PADW + out] = v.y;
                sW[(kv * 4 + 2) * PADW + out] = v.z;
                sW[(kv * 4 + 3) * PADW + out] = v.w;
            }
            __syncthreads();
            #pragma unroll 4
            for (int k = 0; k < 32; k++) {
                // node pairs: direct 8B-packed loads (2 x LDS.128)
                ulonglong2 aa = *(const ulonglong2*)&sA[k * PAD + ng * 8];
                ulonglong2 ab = *(const ulonglong2*)&sA[k * PAD + ng * 8 + 4];
                unsigned long long a2[4] = {aa.x, aa.y, ab.x, ab.y};
                unsigned long long w2[TO];
                if (TO == 8) {
                    float4 w0 = *(const float4*)&sW[k * PADW + og * TO];
                    float4 w1 = *(const float4*)&sW[k * PADW + og * TO + 4];
                    w2[0] = rep2(w0.x); w2[1] = rep2(w0.y);
                    w2[2] = rep2(w0.z); w2[3] = rep2(w0.w);
                    w2[4] = rep2(w1.x); w2[5] = rep2(w1.y);
                    w2[6] = rep2(w1.z); w2[7] = rep2(w1.w);
                } else {
                    float4 w0 = *(const float4*)&sW[k * PADW + og * TO];
                    w2[0] = rep2(w0.x); w2[1] = rep2(w0.y);
                    w2[2] = rep2(w0.z); w2[3] = rep2(w0.w);
                }
                #pragma unroll
                for (int i = 0; i < 4; i++)
                    #pragma unroll
                    for (int j = 0; j < TO; j++)
                        fma2(acc2[i][j], a2[i], w2[j]);
            }
        }
    }

    // epilogue: bias (+ReLU+LN), write
    float bi[TO], gg[TO], bb[TO];
    #pragma unroll
    for (int j = 0; j < TO; j++) {
        int o = og * TO + j;
        bi[j] = bias[o];
        if (LN) { gg[j] = gamma[o]; bb[j] = beta[o]; }
    }
    #pragma unroll
    for (int i = 0; i < 8; i++) {
        int gn = nodeBase + ng * 8 + i;
        float r[TO];
        #pragma unroll
        for (int j = 0; j < TO; j++) {
            float2 p = unpack2(acc2[i >> 1][j]);
            r[j] = ((i & 1) ? p.y : p.x) + bi[j];
        }
        if (LN) {
            #pragma unroll
            for (int j = 0; j < TO; j++) r[j] = fmaxf(r[j], 0.f);
            float s = 0.f;
            #pragma unroll
            for (int j = 0; j < TO; j++) s += r[j];
            #pragma unroll
            for (int o = 8; o; o >>= 1) s += __shfl_xor_sync(0xFFFFFFFFu, s, o);
            float mu = s * (1.f / (float)DOUT);
            float q = 0.f;
            #pragma unroll
            for (int j = 0; j < TO; j++) {
                r[j] -= mu;
                q += r[j] * r[j];
            }
            #pragma unroll
            for (int o = 8; o; o >>= 1) q += __shfl_xor_sync(0xFFFFFFFFu, q, o);
            float rstd = rsqrtf(q * (1.f / (float)DOUT) + 1e-5f);
            #pragma unroll
            for (int j = 0; j < TO; j++) r[j] = r[j] * rstd * gg[j] + bb[j];
        }
        if (gn < nNodes) {
            float* dst = Y + (size_t)gn * DOUT + og * TO;
            #pragma unroll
            for (int j4 = 0; j4 < TO; j4 += 4)
                *(float4*)(dst + j4) = make_float4(r[j4], r[j4 + 1], r[j4 + 2], r[j4 + 3]);
        }
    }
}

// ---------------- launch -----------------------------------------------------
extern "C" void kernel_launch(void* const* d_in, const int* in_sizes, int n_in,
                              void* d_out, int out_size) {
    const float* x = (const float*)d_in[0];
    const long long* edges = (const long long*)d_in[1];
    const int E = in_sizes[1] / 2;
    const int N = in_sizes[0] / FDIM;

    const float *Wl0, *Wr0, *b0, *g0, *be0;
    const float *Wl1, *Wr1, *b1, *g1, *be1;
    const float *Wl2, *Wr2, *b2;
    if (in_sizes[5] == 16384) {
        Wl0 = (const float*)d_in[2];  Wr0 = (const float*)d_in[3];  b0 = (const float*)d_in[4];
        Wl1 = (const float*)d_in[5];  Wr1 = (const float*)d_in[6];  b1 = (const float*)d_in[7];
        Wl2 = (const float*)d_in[8];  Wr2 = (const float*)d_in[9];  b2 = (const float*)d_in[10];
        g0  = (const float*)d_in[11]; be0 = (const float*)d_in[12];
        g1  = (const float*)d_in[13]; be1 = (const float*)d_in[14];
    } else {
        Wl0 = (const float*)d_in[2];  Wr0 = (const float*)d_in[3];  b0 = (const float*)d_in[4];
        g0  = (const float*)d_in[5];  be0 = (const float*)d_in[6];
        Wl1 = (const float*)d_in[7];  Wr1 = (const float*)d_in[8];  b1 = (const float*)d_in[9];
        g1  = (const float*)d_in[10]; be1 = (const float*)d_in[11];
        Wl2 = (const float*)d_in[12]; Wr2 = (const float*)d_in[13]; b2 = (const float*)d_in[14];
    }
    float* out = (float*)d_out;

    const int TB = 256;
    const int gE = (E + TB - 1) / TB;
    const int gN = (N + TB - 1) / TB;      // 256-thread node-sized grids
    const int gWarp = (N * 32 + TB - 1) / TB;
    const int gGemm = (N + 127) / 128;

    // CSR build
    k_zero_detect<<<gN, TB>>>(edges, E, N);
    k_hist<<<gE, TB>>>(edges, E);
    k_blockscan<<<gN, TB>>>(N);
    k_scan_bsum<<<1, 512>>>(gN);
    k_finalize<<<gN, TB>>>(N);
    k_fill<<<gE, TB>>>(edges, E);

    // Layer 0: agg(x) -> gemm+relu+LN -> hA
    k_aggregate<<<gWarp, TB>>>(x, 3, N);
    k_gemm<128, true><<<gGemm, TB>>>(x, 3, Wl0, Wr0, b0, g0, be0, nullptr, 1, N);

    // Layer 1: agg(hA) -> gemm+relu+LN -> hB
    k_aggregate<<<gWarp, TB>>>(nullptr, 1, N);
    k_gemm<128, true><<<gGemm, TB>>>(nullptr, 1, Wl1, Wr1, b1, g1, be1, nullptr, 2, N);

    // Layer 2: agg(hB) -> gemm -> d_out
    k_aggregate<<<gWarp, TB>>>(nullptr, 2, N);
    k_gemm<64, false><<<gGemm, TB>>>(nullptr, 2, Wl2, Wr2, b2, nullptr, nullptr, out, 3, N);
}

// round 4
// speedup vs baseline: 1.5685x; 1.2992x over previous
#include <cuda_runtime.h>
#include <cuda_bf16.h>
#include <cstdint>

#define NMAX 100000
#define EMAX 1600000
#define FDIM 128

// ---------------- device scratch --------------------------------------------
__device__ int   g_ptr[NMAX + 1];
__device__ int   g_cursor[NMAX];
__device__ int   g_cnt[NMAX];
__device__ int   g_scan[NMAX];
__device__ int   g_bsum[512];
__device__ int   g_boff[512];
__device__ int   g_col[EMAX];
__device__ float g_P  [(size_t)NMAX * 256];   // [node][Pl(0..D-1) | Pr(D..2D-1)]
__device__ float g_hA [(size_t)NMAX * FDIM];
__device__ float g_hB [(size_t)NMAX * FDIM];
__device__ int   g_is32;

__device__ __forceinline__ const float* pick_c(int s, const float* ext) {
    return s == 1 ? g_hA : s == 2 ? g_hB : ext;
}
__device__ __forceinline__ float* pick_m(int s, float* ext) {
    return s == 1 ? g_hA : s == 2 ? g_hB : ext;
}

// ---------------- tf32 helpers -----------------------------------------------
__device__ __forceinline__ uint32_t f2tf(float x) {
    uint32_t r;
    asm("cvt.rna.tf32.f32 %0, %1;" : "=r"(r) : "f"(x));
    return r;
}
__device__ __forceinline__ void mma_tf32(float* d, const uint32_t* a, const uint32_t* b) {
    asm volatile(
        "mma.sync.aligned.m16n8k8.row.col.f32.tf32.tf32.f32 "
        "{%0,%1,%2,%3}, {%4,%5,%6,%7}, {%8,%9}, {%0,%1,%2,%3};"
        : "+f"(d[0]), "+f"(d[1]), "+f"(d[2]), "+f"(d[3])
        : "r"(a[0]), "r"(a[1]), "r"(a[2]), "r"(a[3]), "r"(b[0]), "r"(b[1]));
}

// ---------------- CSR build --------------------------------------------------
__global__ void k_zero_detect(const long long* __restrict__ e, int E, int n) {
    int i = blockIdx.x * blockDim.x + threadIdx.x;
    if (i < n) g_cnt[i] = 0;
    if (i == 0) {
        int bad = 0;
        int lim = E < 64 ? E : 64;
        for (int j = 0; j < lim; j++) {
            long long v = e[j];
            if (v < 0 || v >= (long long)n) bad = 1;
        }
        g_is32 = bad;
    }
}

__global__ void k_hist(const long long* __restrict__ e64, int E) {
    int i = blockIdx.x * blockDim.x + threadIdx.x;
    if (i >= E) return;
    int d;
    if (!g_is32) d = (int)e64[(size_t)E + i];
    else         d = ((const int*)e64)[(size_t)E + i];
    atomicAdd(&g_cnt[d], 1);
}

__global__ void k_blockscan(int n) {
    __shared__ int wsum[8];
    int i = blockIdx.x * 256 + threadIdx.x;
    int lane = threadIdx.x & 31, wid = threadIdx.x >> 5;
    int v = (i < n) ? g_cnt[i] : 0;
    #pragma unroll
    for (int o = 1; o < 32; o <<= 1) {
        int u = __shfl_up_sync(0xFFFFFFFFu, v, o);
        if (lane >= o) v += u;
    }
    if (lane == 31) wsum[wid] = v;
    __syncthreads();
    if (wid == 0 && lane < 8) {
        int w = wsum[lane];
        #pragma unroll
        for (int o = 1; o < 8; o <<= 1) {
            int u = __shfl_up_sync(0xFFu, w, o);
            if (lane >= o) w += u;
        }
        wsum[lane] = w;
    }
    __syncthreads();
    int incl = v + (wid > 0 ? wsum[wid - 1] : 0);
    if (i < n) g_scan[i] = incl;
    if (threadIdx.x == 255) g_bsum[blockIdx.x] = incl;
}

__global__ void k_scan_bsum(int nb) {
    __shared__ int wsum[16];
    int t = threadIdx.x;
    int lane = t & 31, wid = t >> 5;
    if (nb > 512) nb = 512;
    int v = (t < nb) ? g_bsum[t] : 0;
    int orig = v;
    #pragma unroll
    for (int o = 1; o < 32; o <<= 1) {
        int u = __shfl_up_sync(0xFFFFFFFFu, v, o);
        if (lane >= o) v += u;
    }
    if (lane == 31) wsum[wid] = v;
    __syncthreads();
    if (wid == 0 && lane < 16) {
        int w = wsum[lane];
        #pragma unroll
        for (int o = 1; o < 16; o <<= 1) {
            int u = __shfl_up_sync(0xFFFFu, w, o);
            if (lane >= o) w += u;
        }
        wsum[lane] = w;
    }
    __syncthreads();
    int incl = v + (wid > 0 ? wsum[wid - 1] : 0);
    if (t < nb) g_boff[t] = incl - orig;
}

__global__ void k_finalize(int n) {
    int i = blockIdx.x * 256 + threadIdx.x;
    if (i >= n) return;
    int incl = g_scan[i] + g_boff[blockIdx.x];
    g_ptr[i + 1] = incl;
    g_cursor[i] = incl - g_cnt[i];
    if (i == 0) g_ptr[0] = 0;
}

__global__ void k_fill(const long long* __restrict__ e64, int E) {
    int i = blockIdx.x * blockDim.x + threadIdx.x;
    if (i >= E) return;
    int s, d;
    if (!g_is32) {
        s = (int)e64[i];
        d = (int)e64[(size_t)E + i];
    } else {
        const int* e32 = (const int*)e64;
        s = e32[i];
        d = e32[(size_t)E + i];
    }
    int pos = atomicAdd(&g_cursor[d], 1);
    g_col[pos] = s;
}

// ---------------- GEMM (tf32 tensor cores): P = X @ [Wl;Wr]^T ----------------
// CTA: 128 nodes x 128 cols, 8 warps (2m x 4n), warp tile 64x32.
// K = 128 processed in 4 chunks of 32; m16n8k8 fragments from padded smem.
template <int DOUT>
__global__ __launch_bounds__(256)
void k_gemm_tc(const float* __restrict__ extX, int selX,
               const float* __restrict__ Wl, const float* __restrict__ Wr,
               int nNodes) {
    constexpr int STR  = 2 * DOUT;     // g_P row stride
    constexpr int SPAD = 44;           // smem row stride (uint32), conflict-free
    __shared__ uint32_t sA[128 * SPAD];
    __shared__ uint32_t sB[128 * SPAD];

    const float* __restrict__ X = pick_c(selX, extX);

    const int tx = threadIdx.x;
    const int warp = tx >> 5;
    const int lane = tx & 31;
    const int wm = warp & 1;           // 0..1 -> 64-row half
    const int wn = warp >> 1;          // 0..3 -> 32-col quarter
    const int g = lane >> 2;           // 0..7
    const int t = lane & 3;            // 0..3
    const int nodeBase = blockIdx.x * 128;
    const int colBase = blockIdx.y * 128;

    float acc[4][4][4];
    #pragma unroll
    for (int mt = 0; mt < 4; mt++)
        #pragma unroll
        for (int nt = 0; nt < 4; nt++)
            #pragma unroll
            for (int r = 0; r < 4; r++) acc[mt][nt][r] = 0.f;

    for (int kb = 0; kb < FDIM; kb += 32) {
        __syncthreads();
        // A tile: 128 nodes x 32 k
        #pragma unroll
        for (int r = 0; r < 4; r++) {
            int lin = tx + r * 256;
            int node = lin >> 3;
            int kv = lin & 7;
            int gn = nodeBase + node;
            float4 v = make_float4(0.f, 0.f, 0.f, 0.f);
            if (gn < nNodes)
                v = *(const float4*)(X + (size_t)gn * FDIM + kb + kv * 4);
            uint4 u = make_uint4(f2tf(v.x), f2tf(v.y), f2tf(v.z), f2tf(v.w));
            *(uint4*)&sA[node * SPAD + kv * 4] = u;
        }
        // B tile: 128 stacked-weight rows x 32 k
        #pragma unroll
        for (int r = 0; r < 4; r++) {
            int lin = tx + r * 256;
            int col = lin >> 3;
            int kv = lin & 7;
            int wrow = colBase + col;
            const float* Wsrc = (wrow < DOUT) ? (Wl + (size_t)wrow * FDIM)
                                              : (Wr + (size_t)(wrow - DOUT) * FDIM);
            float4 v = *(const float4*)(Wsrc + kb + kv * 4);
            uint4 u = make_uint4(f2tf(v.x), f2tf(v.y), f2tf(v.z), f2tf(v.w));
            *(uint4*)&sB[col * SPAD + kv * 4] = u;
        }
        __syncthreads();

        #pragma unroll
        for (int ks = 0; ks < 4; ks++) {
            uint32_t afrag[4][4];
            #pragma unroll
            for (int mt = 0; mt < 4; mt++) {
                int row = wm * 64 + mt * 16 + g;
                afrag[mt][0] = sA[row * SPAD + ks * 8 + t];
                afrag[mt][1] = sA[(row + 8) * SPAD + ks * 8 + t];
                afrag[mt][2] = sA[row * SPAD + ks * 8 + t + 4];
                afrag[mt][3] = sA[(row + 8) * SPAD + ks * 8 + t + 4];
            }
            uint32_t bfrag[4][2];
            #pragma unroll
            for (int nt = 0; nt < 4; nt++) {
                int coln = wn * 32 + nt * 8 + g;
                bfrag[nt][0] = sB[coln * SPAD + ks * 8 + t];
                bfrag[nt][1] = sB[coln * SPAD + ks * 8 + t + 4];
            }
            #pragma unroll
            for (int mt = 0; mt < 4; mt++)
                #pragma unroll
                for (int nt = 0; nt < 4; nt++)
                    mma_tf32(acc[mt][nt], afrag[mt], bfrag[nt]);
        }
    }

    // epilogue: write P
    #pragma unroll
    for (int mt = 0; mt < 4; mt++) {
        int row0 = nodeBase + wm * 64 + mt * 16 + g;
        #pragma unroll
        for (int nt = 0; nt < 4; nt++) {
            int col = colBase + wn * 32 + nt * 8 + 2 * t;
            if (row0 < nNodes)
                *(float2*)&g_P[(size_t)row0 * STR + col] =
                    make_float2(acc[mt][nt][0], acc[mt][nt][1]);
            if (row0 + 8 < nNodes)
                *(float2*)&g_P[(size_t)(row0 + 8) * STR + col] =
                    make_float2(acc[mt][nt][2], acc[mt][nt][3]);
        }
    }
}

// ---------------- fused aggregate + Pr + bias (+ReLU+LN) --------------------
// warp per node; out = f(mean_gather(Pl) + Pr + b)
template <int D, bool LN>
__global__ void k_agg_ep(const float* __restrict__ bias,
                         const float* __restrict__ gamma,
                         const float* __restrict__ beta,
                         float* __restrict__ extOut, int selOut, int nNodes) {
    constexpr int STR = 2 * D;
    int node = (blockIdx.x * blockDim.x + threadIdx.x) >> 5;
    int lane = threadIdx.x & 31;
    if (node >= nNodes) return;
    float* __restrict__ Out = pick_m(selOut, extOut);

    int start = g_ptr[node], end = g_ptr[node + 1];
    float dinv = 1.f / fmaxf((float)(end - start), 1.f);

    if (D == 128) {
        float4 s = make_float4(0.f, 0.f, 0.f, 0.f);
        for (int i = start; i < end; i++) {
            int src = g_col[i];
            float4 v = *(const float4*)(g_P + (size_t)src * STR + lane * 4);
            s.x += v.x; s.y += v.y; s.z += v.z; s.w += v.w;
        }
        float4 pr = *(const float4*)(g_P + (size_t)node * STR + D + lane * 4);
        float4 b4 = *(const float4*)(bias + lane * 4);
        float r0 = s.x * dinv + pr.x + b4.x;
        float r1 = s.y * dinv + pr.y + b4.y;
        float r2 = s.z * dinv + pr.z + b4.z;
        float r3 = s.w * dinv + pr.w + b4.w;
        if (LN) {
            r0 = fmaxf(r0, 0.f); r1 = fmaxf(r1, 0.f);
            r2 = fmaxf(r2, 0.f); r3 = fmaxf(r3, 0.f);
            float sm = r0 + r1 + r2 + r3;
            #pragma unroll
            for (int o = 16; o; o >>= 1) sm += __shfl_xor_sync(0xFFFFFFFFu, sm, o);
            float mu = sm * (1.f / 128.f);
            r0 -= mu; r1 -= mu; r2 -= mu; r3 -= mu;
            float q = r0 * r0 + r1 * r1 + r2 * r2 + r3 * r3;
            #pragma unroll
            for (int o = 16; o; o >>= 1) q += __shfl_xor_sync(0xFFFFFFFFu, q, o);
            float rstd = rsqrtf(q * (1.f / 128.f) + 1e-5f);
            float4 g4 = *(const float4*)(gamma + lane * 4);
            float4 be4 = *(const float4*)(beta + lane * 4);
            r0 = r0 * rstd * g4.x + be4.x;
            r1 = r1 * rstd * g4.y + be4.y;
            r2 = r2 * rstd * g4.z + be4.z;
            r3 = r3 * rstd * g4.w + be4.w;
        }
        *(float4*)(Out + (size_t)node * D + lane * 4) = make_float4(r0, r1, r2, r3);
    } else {
        // D == 64, no LN (final layer)
        float2 s = make_float2(0.f, 0.f);
        for (int i = start; i < end; i++) {
            int src = g_col[i];
            float2 v = *(const float2*)(g_P + (size_t)src * STR + lane * 2);
            s.x += v.x; s.y += v.y;
        }
        float2 pr = *(const float2*)(g_P + (size_t)node * STR + D + lane * 2);
        float2 b2 = *(const float2*)(bias + lane * 2);
        float r0 = s.x * dinv + pr.x + b2.x;
        float r1 = s.y * dinv + pr.y + b2.y;
        *(float2*)(Out + (size_t)node * D + lane * 2) = make_float2(r0, r1);
    }
}

// ---------------- launch -----------------------------------------------------
extern "C" void kernel_launch(void* const* d_in, const int* in_sizes, int n_in,
                              void* d_out, int out_size) {
    const float* x = (const float*)d_in[0];
    const long long* edges = (const long long*)d_in[1];
    const int E = in_sizes[1] / 2;
    const int N = in_sizes[0] / FDIM;

    const float *Wl0, *Wr0, *b0, *g0, *be0;
    const float *Wl1, *Wr1, *b1, *g1, *be1;
    const float *Wl2, *Wr2, *b2;
    if (in_sizes[5] == 16384) {
        Wl0 = (const float*)d_in[2];  Wr0 = (const float*)d_in[3];  b0 = (const float*)d_in[4];
        Wl1 = (const float*)d_in[5];  Wr1 = (const float*)d_in[6];  b1 = (const float*)d_in[7];
        Wl2 = (const float*)d_in[8];  Wr2 = (const float*)d_in[9];  b2 = (const float*)d_in[10];
        g0  = (const float*)d_in[11]; be0 = (const float*)d_in[12];
        g1  = (const float*)d_in[13]; be1 = (const float*)d_in[14];
    } else {
        Wl0 = (const float*)d_in[2];  Wr0 = (const float*)d_in[3];  b0 = (const float*)d_in[4];
        g0  = (const float*)d_in[5];  be0 = (const float*)d_in[6];
        Wl1 = (const float*)d_in[7];  Wr1 = (const float*)d_in[8];  b1 = (const float*)d_in[9];
        g1  = (const float*)d_in[10]; be1 = (const float*)d_in[11];
        Wl2 = (const float*)d_in[12]; Wr2 = (const float*)d_in[13]; b2 = (const float*)d_in[14];
    }
    float* out = (float*)d_out;

    const int TB = 256;
    const int gE = (E + TB - 1) / TB;
    const int gN = (N + TB - 1) / TB;
    const int gWarp = (N * 32 + TB - 1) / TB;
    const int gM = (N + 127) / 128;

    // CSR build
    k_zero_detect<<<gN, TB>>>(edges, E, N);
    k_hist<<<gE, TB>>>(edges, E);
    k_blockscan<<<gN, TB>>>(N);
    k_scan_bsum<<<1, 512>>>(gN);
    k_finalize<<<gN, TB>>>(N);
    k_fill<<<gE, TB>>>(edges, E);

    // Layer 0: P = x @ [Wl0;Wr0]^T ; h = LN(ReLU(mean(Pl)+Pr+b))
    k_gemm_tc<128><<<dim3(gM, 2), TB>>>(x, 3, Wl0, Wr0, N);
    k_agg_ep<128, true><<<gWarp, TB>>>(b0, g0, be0, nullptr, 1, N);

    // Layer 1
    k_gemm_tc<128><<<dim3(gM, 2), TB>>>(nullptr, 1, Wl1, Wr1, N);
    k_agg_ep<128, true><<<gWarp, TB>>>(b1, g1, be1, nullptr, 2, N);

    // Layer 2 (DOUT=64, no ReLU/LN)
    k_gemm_tc<64><<<dim3(gM, 1), TB>>>(nullptr, 2, Wl2, Wr2, N);
    k_agg_ep<64, false><<<gWarp, TB>>>(b2, nullptr, nullptr, out, 3, N);
}

// round 5
// speedup vs baseline: 2.0121x; 1.2828x over previous
#include <cuda_runtime.h>
#include <cuda_bf16.h>
#include <cstdint>

#define NMAX 100000
#define EMAX 1600000
#define FDIM 128

// ---------------- device scratch --------------------------------------------
__device__ int   g_ptr[NMAX + 1];
__device__ int   g_cursor[NMAX];
__device__ int   g_cnt[NMAX];
__device__ int   g_scan[NMAX];
__device__ int   g_bsum[512];
__device__ int   g_boff[512];
__device__ int   g_col[EMAX];
__device__ float g_P  [(size_t)NMAX * 256];   // [node][Pl(0..D-1) | Pr(D..2D-1)]
__device__ float g_hA [(size_t)NMAX * FDIM];
__device__ float g_hB [(size_t)NMAX * FDIM];
__device__ int   g_is32;

__device__ __forceinline__ const float* pick_c(int s, const float* ext) {
    return s == 1 ? g_hA : s == 2 ? g_hB : ext;
}
__device__ __forceinline__ float* pick_m(int s, float* ext) {
    return s == 1 ? g_hA : s == 2 ? g_hB : ext;
}

// ---------------- tf32 helpers -----------------------------------------------
__device__ __forceinline__ uint32_t f2tf(float x) {
    uint32_t r;
    asm("cvt.rna.tf32.f32 %0, %1;" : "=r"(r) : "f"(x));
    return r;
}
__device__ __forceinline__ void mma_tf32(float* d, const uint32_t* a, const uint32_t* b) {
    asm volatile(
        "mma.sync.aligned.m16n8k8.row.col.f32.tf32.tf32.f32 "
        "{%0,%1,%2,%3}, {%4,%5,%6,%7}, {%8,%9}, {%0,%1,%2,%3};"
        : "+f"(d[0]), "+f"(d[1]), "+f"(d[2]), "+f"(d[3])
        : "r"(a[0]), "r"(a[1]), "r"(a[2]), "r"(a[3]), "r"(b[0]), "r"(b[1]));
}

// ---------------- CSR build --------------------------------------------------
__global__ void k_zero_detect(const long long* __restrict__ e, int E, int n) {
    int i = blockIdx.x * blockDim.x + threadIdx.x;
    if (i < n) g_cnt[i] = 0;
    if (i == 0) {
        int bad = 0;
        int lim = E < 64 ? E : 64;
        for (int j = 0; j < lim; j++) {
            long long v = e[j];
            if (v < 0 || v >= (long long)n) bad = 1;
        }
        g_is32 = bad;
    }
}

__global__ void k_hist(const long long* __restrict__ e64, int E) {
    int i = blockIdx.x * blockDim.x + threadIdx.x;
    if (i >= E) return;
    int d;
    if (!g_is32) d = (int)e64[(size_t)E + i];
    else         d = ((const int*)e64)[(size_t)E + i];
    atomicAdd(&g_cnt[d], 1);
}

__global__ void k_blockscan(int n) {
    __shared__ int wsum[8];
    int i = blockIdx.x * 256 + threadIdx.x;
    int lane = threadIdx.x & 31, wid = threadIdx.x >> 5;
    int v = (i < n) ? g_cnt[i] : 0;
    #pragma unroll
    for (int o = 1; o < 32; o <<= 1) {
        int u = __shfl_up_sync(0xFFFFFFFFu, v, o);
        if (lane >= o) v += u;
    }
    if (lane == 31) wsum[wid] = v;
    __syncthreads();
    if (wid == 0 && lane < 8) {
        int w = wsum[lane];
        #pragma unroll
        for (int o = 1; o < 8; o <<= 1) {
            int u = __shfl_up_sync(0xFFu, w, o);
            if (lane >= o) w += u;
        }
        wsum[lane] = w;
    }
    __syncthreads();
    int incl = v + (wid > 0 ? wsum[wid - 1] : 0);
    if (i < n) g_scan[i] = incl;
    if (threadIdx.x == 255) g_bsum[blockIdx.x] = incl;
}

__global__ void k_scan_bsum(int nb) {
    __shared__ int wsum[16];
    int t = threadIdx.x;
    int lane = t & 31, wid = t >> 5;
    if (nb > 512) nb = 512;
    int v = (t < nb) ? g_bsum[t] : 0;
    int orig = v;
    #pragma unroll
    for (int o = 1; o < 32; o <<= 1) {
        int u = __shfl_up_sync(0xFFFFFFFFu, v, o);
        if (lane >= o) v += u;
    }
    if (lane == 31) wsum[wid] = v;
    __syncthreads();
    if (wid == 0 && lane < 16) {
        int w = wsum[lane];
        #pragma unroll
        for (int o = 1; o < 16; o <<= 1) {
            int u = __shfl_up_sync(0xFFFFu, w, o);
            if (lane >= o) w += u;
        }
        wsum[lane] = w;
    }
    __syncthreads();
    int incl = v + (wid > 0 ? wsum[wid - 1] : 0);
    if (t < nb) g_boff[t] = incl - orig;
}

__global__ void k_finalize(int n) {
    int i = blockIdx.x * 256 + threadIdx.x;
    if (i >= n) return;
    int incl = g_scan[i] + g_boff[blockIdx.x];
    g_ptr[i + 1] = incl;
    g_cursor[i] = incl - g_cnt[i];
    if (i == 0) g_ptr[0] = 0;
}

__global__ void k_fill(const long long* __restrict__ e64, int E) {
    int i = blockIdx.x * blockDim.x + threadIdx.x;
    if (i >= E) return;
    int s, d;
    if (!g_is32) {
        s = (int)e64[i];
        d = (int)e64[(size_t)E + i];
    } else {
        const int* e32 = (const int*)e64;
        s = e32[i];
        d = e32[(size_t)E + i];
    }
    int pos = atomicAdd(&g_cursor[d], 1);
    g_col[pos] = s;
}

// ---------------- GEMM (tf32 tensor cores): P = X @ [Wl;Wr]^T ----------------
// CTA: 128 nodes x 128 cols. sB holds the full K=128 weight tile (loaded once);
// sA double-buffers 32-k chunks with register-staged prefetch.
#define SPADB 132
#define SPADA 36
#define SMEM_GEMM ((128 * SPADB + 2 * 128 * SPADA) * 4)

template <int DOUT>
__global__ __launch_bounds__(256, 2)
void k_gemm_tc(const float* __restrict__ extX, int selX,
               const float* __restrict__ Wl, const float* __restrict__ Wr,
               int nNodes) {
    constexpr int STR = 2 * DOUT;
    extern __shared__ uint32_t smem[];
    uint32_t* sB = smem;                       // [col][k] 128 x 132
    uint32_t* sA = smem + 128 * SPADB;         // 2 x [node][k32] 128 x 36

    const float* __restrict__ X = pick_c(selX, extX);

    const int tx = threadIdx.x;
    const int warp = tx >> 5;
    const int lane = tx & 31;
    const int wm = warp & 1;
    const int wn = warp >> 1;
    const int g = lane >> 2;
    const int t = lane & 3;
    const int nodeBase = blockIdx.x * 128;
    const int colBase = blockIdx.y * 128;

    // ---- load full B tile (128 cols x 128 k) ----
    #pragma unroll
    for (int r = 0; r < 16; r++) {
        int lin = tx + r * 256;
        int col = lin >> 5;                    // 32 float4 per row
        int kv = lin & 31;
        int wrow = colBase + col;
        const float* Wsrc = (wrow < DOUT) ? (Wl + (size_t)wrow * FDIM)
                                          : (Wr + (size_t)(wrow - DOUT) * FDIM);
        float4 v = *(const float4*)(Wsrc + kv * 4);
        uint4 u = make_uint4(f2tf(v.x), f2tf(v.y), f2tf(v.z), f2tf(v.w));
        *(uint4*)&sB[col * SPADB + kv * 4] = u;
    }

    // ---- prologue: A chunk 0 -> regs -> sA buf0 ----
    float4 stage[4];
    #pragma unroll
    for (int r = 0; r < 4; r++) {
        int lin = tx + r * 256;
        int node = lin >> 3;
        int kv = lin & 7;
        int gn = nodeBase + node;
        stage[r] = make_float4(0.f, 0.f, 0.f, 0.f);
        if (gn < nNodes)
            stage[r] = *(const float4*)(X + (size_t)gn * FDIM + kv * 4);
    }
    #pragma unroll
    for (int r = 0; r < 4; r++) {
        int lin = tx + r * 256;
        int node = lin >> 3;
        int kv = lin & 7;
        uint4 u = make_uint4(f2tf(stage[r].x), f2tf(stage[r].y),
                             f2tf(stage[r].z), f2tf(stage[r].w));
        *(uint4*)&sA[node * SPADA + kv * 4] = u;
    }

    float acc[4][4][4];
    #pragma unroll
    for (int mt = 0; mt < 4; mt++)
        #pragma unroll
        for (int nt = 0; nt < 4; nt++)
            #pragma unroll
            for (int r = 0; r < 4; r++) acc[mt][nt][r] = 0.f;

    #pragma unroll
    for (int c = 0; c < 4; c++) {
        __syncthreads();
        // prefetch next A chunk into regs (LDGs overlap compute below)
        if (c < 3) {
            #pragma unroll
            for (int r = 0; r < 4; r++) {
                int lin = tx + r * 256;
                int node = lin >> 3;
                int kv = lin & 7;
                int gn = nodeBase + node;
                stage[r] = make_float4(0.f, 0.f, 0.f, 0.f);
                if (gn < nNodes)
                    stage[r] = *(const float4*)(X + (size_t)gn * FDIM + (c + 1) * 32 + kv * 4);
            }
        }
        const uint32_t* curA = sA + (c & 1) * 128 * SPADA;
        #pragma unroll
        for (int ks = 0; ks < 4; ks++) {
            int kB = c * 32 + ks * 8;
            uint32_t afrag[4][4];
            #pragma unroll
            for (int mt = 0; mt < 4; mt++) {
                int row = wm * 64 + mt * 16 + g;
                afrag[mt][0] = curA[row * SPADA + ks * 8 + t];
                afrag[mt][1] = curA[(row + 8) * SPADA + ks * 8 + t];
                afrag[mt][2] = curA[row * SPADA + ks * 8 + t + 4];
                afrag[mt][3] = curA[(row + 8) * SPADA + ks * 8 + t + 4];
            }
            uint32_t bfrag[4][2];
            #pragma unroll
            for (int nt = 0; nt < 4; nt++) {
                int coln = wn * 32 + nt * 8 + g;
                bfrag[nt][0] = sB[coln * SPADB + kB + t];
                bfrag[nt][1] = sB[coln * SPADB + kB + t + 4];
            }
            #pragma unroll
            for (int mt = 0; mt < 4; mt++)
                #pragma unroll
                for (int nt = 0; nt < 4; nt++)
                    mma_tf32(acc[mt][nt], afrag[mt], bfrag[nt]);
        }
        // stage -> other buffer (prev compute on it finished before this
        // iteration's __syncthreads)
        if (c < 3) {
            uint32_t* nxtA = sA + ((c + 1) & 1) * 128 * SPADA;
            #pragma unroll
            for (int r = 0; r < 4; r++) {
                int lin = tx + r * 256;
                int node = lin >> 3;
                int kv = lin & 7;
                uint4 u = make_uint4(f2tf(stage[r].x), f2tf(stage[r].y),
                                     f2tf(stage[r].z), f2tf(stage[r].w));
                *(uint4*)&nxtA[node * SPADA + kv * 4] = u;
            }
        }
    }

    // epilogue: write P
    #pragma unroll
    for (int mt = 0; mt < 4; mt++) {
        int row0 = nodeBase + wm * 64 + mt * 16 + g;
        #pragma unroll
        for (int nt = 0; nt < 4; nt++) {
            int col = colBase + wn * 32 + nt * 8 + 2 * t;
            if (row0 < nNodes)
                *(float2*)&g_P[(size_t)row0 * STR + col] =
                    make_float2(acc[mt][nt][0], acc[mt][nt][1]);
            if (row0 + 8 < nNodes)
                *(float2*)&g_P[(size_t)(row0 + 8) * STR + col] =
                    make_float2(acc[mt][nt][2], acc[mt][nt][3]);
        }
    }
}

// ---------------- fused aggregate + Pr + bias (+ReLU+LN) --------------------
// warp per node; out = f(mean_gather(Pl) + Pr + b); edge loop unrolled x2.
template <int D, bool LN>
__global__ void k_agg_ep(const float* __restrict__ bias,
                         const float* __restrict__ gamma,
                         const float* __restrict__ beta,
                         float* __restrict__ extOut, int selOut, int nNodes) {
    constexpr int STR = 2 * D;
    int node = (blockIdx.x * blockDim.x + threadIdx.x) >> 5;
    int lane = threadIdx.x & 31;
    if (node >= nNodes) return;
    float* __restrict__ Out = pick_m(selOut, extOut);

    int start = g_ptr[node], end = g_ptr[node + 1];
    float dinv = 1.f / fmaxf((float)(end - start), 1.f);

    if (D == 128) {
        float4 s0 = make_float4(0.f, 0.f, 0.f, 0.f);
        float4 s1 = make_float4(0.f, 0.f, 0.f, 0.f);
        int i = start;
        for (; i + 1 < end; i += 2) {
            int a = g_col[i], b = g_col[i + 1];
            float4 va = *(const float4*)(g_P + (size_t)a * STR + lane * 4);
            float4 vb = *(const float4*)(g_P + (size_t)b * STR + lane * 4);
            s0.x += va.x; s0.y += va.y; s0.z += va.z; s0.w += va.w;
            s1.x += vb.x; s1.y += vb.y; s1.z += vb.z; s1.w += vb.w;
        }
        if (i < end) {
            int a = g_col[i];
            float4 va = *(const float4*)(g_P + (size_t)a * STR + lane * 4);
            s0.x += va.x; s0.y += va.y; s0.z += va.z; s0.w += va.w;
        }
        float4 pr = *(const float4*)(g_P + (size_t)node * STR + D + lane * 4);
        float4 b4 = *(const float4*)(bias + lane * 4);
        float r0 = (s0.x + s1.x) * dinv + pr.x + b4.x;
        float r1 = (s0.y + s1.y) * dinv + pr.y + b4.y;
        float r2 = (s0.z + s1.z) * dinv + pr.z + b4.z;
        float r3 = (s0.w + s1.w) * dinv + pr.w + b4.w;
        if (LN) {
            r0 = fmaxf(r0, 0.f); r1 = fmaxf(r1, 0.f);
            r2 = fmaxf(r2, 0.f); r3 = fmaxf(r3, 0.f);
            float sm = r0 + r1 + r2 + r3;
            #pragma unroll
            for (int o = 16; o; o >>= 1) sm += __shfl_xor_sync(0xFFFFFFFFu, sm, o);
            float mu = sm * (1.f / 128.f);
            r0 -= mu; r1 -= mu; r2 -= mu; r3 -= mu;
            float q = r0 * r0 + r1 * r1 + r2 * r2 + r3 * r3;
            #pragma unroll
            for (int o = 16; o; o >>= 1) q += __shfl_xor_sync(0xFFFFFFFFu, q, o);
            float rstd = rsqrtf(q * (1.f / 128.f) + 1e-5f);
            float4 g4 = *(const float4*)(gamma + lane * 4);
            float4 be4 = *(const float4*)(beta + lane * 4);
            r0 = r0 * rstd * g4.x + be4.x;
            r1 = r1 * rstd * g4.y + be4.y;
            r2 = r2 * rstd * g4.z + be4.z;
            r3 = r3 * rstd * g4.w + be4.w;
        }
        *(float4*)(Out + (size_t)node * D + lane * 4) = make_float4(r0, r1, r2, r3);
    } else {
        float2 s0 = make_float2(0.f, 0.f);
        float2 s1 = make_float2(0.f, 0.f);
        int i = start;
        for (; i + 1 < end; i += 2) {
            int a = g_col[i], b = g_col[i + 1];
            float2 va = *(const float2*)(g_P + (size_t)a * STR + lane * 2);
            float2 vb = *(const float2*)(g_P + (size_t)b * STR + lane * 2);
            s0.x += va.x; s0.y += va.y;
            s1.x += vb.x; s1.y += vb.y;
        }
        if (i < end) {
            int a = g_col[i];
            float2 va = *(const float2*)(g_P + (size_t)a * STR + lane * 2);
            s0.x += va.x; s0.y += va.y;
        }
        float2 pr = *(const float2*)(g_P + (size_t)node * STR + D + lane * 2);
        float2 b2 = *(const float2*)(bias + lane * 2);
        float r0 = (s0.x + s1.x) * dinv + pr.x + b2.x;
        float r1 = (s0.y + s1.y) * dinv + pr.y + b2.y;
        *(float2*)(Out + (size_t)node * D + lane * 2) = make_float2(r0, r1);
    }
}

// ---------------- launch -----------------------------------------------------
extern "C" void kernel_launch(void* const* d_in, const int* in_sizes, int n_in,
                              void* d_out, int out_size) {
    const float* x = (const float*)d_in[0];
    const long long* edges = (const long long*)d_in[1];
    const int E = in_sizes[1] / 2;
    const int N = in_sizes[0] / FDIM;

    const float *Wl0, *Wr0, *b0, *g0, *be0;
    const float *Wl1, *Wr1, *b1, *g1, *be1;
    const float *Wl2, *Wr2, *b2;
    if (in_sizes[5] == 16384) {
        Wl0 = (const float*)d_in[2];  Wr0 = (const float*)d_in[3];  b0 = (const float*)d_in[4];
        Wl1 = (const float*)d_in[5];  Wr1 = (const float*)d_in[6];  b1 = (const float*)d_in[7];
        Wl2 = (const float*)d_in[8];  Wr2 = (const float*)d_in[9];  b2 = (const float*)d_in[10];
        g0  = (const float*)d_in[11]; be0 = (const float*)d_in[12];
        g1  = (const float*)d_in[13]; be1 = (const float*)d_in[14];
    } else {
        Wl0 = (const float*)d_in[2];  Wr0 = (const float*)d_in[3];  b0 = (const float*)d_in[4];
        g0  = (const float*)d_in[5];  be0 = (const float*)d_in[6];
        Wl1 = (const float*)d_in[7];  Wr1 = (const float*)d_in[8];  b1 = (const float*)d_in[9];
        g1  = (const float*)d_in[10]; be1 = (const float*)d_in[11];
        Wl2 = (const float*)d_in[12]; Wr2 = (const float*)d_in[13]; b2 = (const float*)d_in[14];
    }
    float* out = (float*)d_out;

    static int smem_set = 0;
    if (!smem_set) {
        cudaFuncSetAttribute(k_gemm_tc<128>,
                             cudaFuncAttributeMaxDynamicSharedMemorySize, SMEM_GEMM);
        cudaFuncSetAttribute(k_gemm_tc<64>,
                             cudaFuncAttributeMaxDynamicSharedMemorySize, SMEM_GEMM);
        smem_set = 1;
    }

    const int TB = 256;
    const int gE = (E + TB - 1) / TB;
    const int gN = (N + TB - 1) / TB;
    const int gWarp = (N * 32 + TB - 1) / TB;
    const int gM = (N + 127) / 128;

    // CSR build
    k_zero_detect<<<gN, TB>>>(edges, E, N);
    k_hist<<<gE, TB>>>(edges, E);
    k_blockscan<<<gN, TB>>>(N);
    k_scan_bsum<<<1, 512>>>(gN);
    k_finalize<<<gN, TB>>>(N);
    k_fill<<<gE, TB>>>(edges, E);

    // Layer 0: P = x @ [Wl0;Wr0]^T ; h = LN(ReLU(mean(Pl)+Pr+b))
    k_gemm_tc<128><<<dim3(gM, 2), TB, SMEM_GEMM>>>(x, 3, Wl0, Wr0, N);
    k_agg_ep<128, true><<<gWarp, TB>>>(b0, g0, be0, nullptr, 1, N);

    // Layer 1
    k_gemm_tc<128><<<dim3(gM, 2), TB, SMEM_GEMM>>>(nullptr, 1, Wl1, Wr1, N);
    k_agg_ep<128, true><<<gWarp, TB>>>(b1, g1, be1, nullptr, 2, N);

    // Layer 2 (DOUT=64, stacked cols = 128 -> one y-block)
    k_gemm_tc<64><<<dim3(gM, 1), TB, SMEM_GEMM>>>(nullptr, 2, Wl2, Wr2, N);
    k_agg_ep<64, false><<<gWarp, TB>>>(b2, nullptr, nullptr, out, 3, N);
}